// round 3
// baseline (speedup 1.0000x reference)
#include <cuda_runtime.h>

// cos(pi*t/16) constants
#define CC1 0.98078528040323044913f
#define CC2 0.92387953251128675613f
#define CC3 0.83146961230254523708f
#define CC4 0.70710678118654752440f
#define CC5 0.55557023301960222474f
#define CC6 0.38268343236508977173f
#define CC7 0.19509032201612826785f

// Four threads per 8x8 tile: thread q = g&3 owns columns {2q, 2q+1}.
// Consecutive lanes own consecutive 8B chunks -> fully coalesced 256B warp transactions.
// Horizontal transform couples the 4 lanes of a tile: butterfly shfl_xor(1)+shfl_xor(2)
// all-reduce per kept zigzag coefficient.
__global__ void __launch_bounds__(128, 6)
jpeg_fused_kernel(const float* __restrict__ in, float* __restrict__ out, int nthr)
{
    const int g = blockIdx.x * blockDim.x + threadIdx.x;
    if (g >= nthr) return;
    const int tile = g >> 2;
    const int q = g & 3;            // column pair index

    // D[k][n] = cos(pi/8 * (n+0.5) * k)
    const float D[8][8] = {
        { 1.f,  1.f,  1.f,  1.f,  1.f,  1.f,  1.f,  1.f},
        { CC1,  CC3,  CC5,  CC7, -CC7, -CC5, -CC3, -CC1},
        { CC2,  CC6, -CC6, -CC2, -CC2, -CC6,  CC6,  CC2},
        { CC3, -CC7, -CC1, -CC5,  CC5,  CC1,  CC7, -CC3},
        { CC4, -CC4, -CC4,  CC4,  CC4, -CC4, -CC4,  CC4},
        { CC5, -CC1,  CC7,  CC3, -CC3, -CC7,  CC1, -CC5},
        { CC6, -CC2,  CC2, -CC6, -CC6,  CC2, -CC2,  CC6},
        { CC7, -CC5,  CC3, -CC1,  CC1, -CC3,  CC5, -CC7}
    };
    // zigzag keep masks are per-row prefixes:
    const int CNTY[7] = {6,5,4,4,3,2,1}; // Y: 25 coeffs, rows 0..6
    const int CNTC[3] = {4,3,2};         // U,V: 9 coeffs, rows 0..2

    // Lane-dependent horizontal constants Wl[l][jj] = D[l][2q+jj], l=1..5.
    // (l=0 row is all 1.0 and handled explicitly.)
    float Wl[6][2];
#pragma unroll
    for (int l = 1; l < 6; ++l) {
        Wl[l][0] = (q & 2) ? ((q & 1) ? D[l][6] : D[l][4])
                           : ((q & 1) ? D[l][2] : D[l][0]);
        Wl[l][1] = (q & 2) ? ((q & 1) ? D[l][7] : D[l][5])
                           : ((q & 1) ? D[l][3] : D[l][1]);
    }

    const int W = 512;
    const int S = 512 * 512;

    const int b  = tile >> 12;       // tiles per image = 64*64
    const int t  = tile & 4095;
    const int ty = t >> 6;
    const int tx = t & 63;

    const size_t base = (size_t)b * (3 * S) + (size_t)(ty * 8) * W
                      + (size_t)(tx * 8) + (size_t)(q * 2);
    const float* pr = in + base;
    const float* pg = pr + S;
    const float* pb = pg + S;

    float Ay[7][2];
    float Au[3][2];
    float Av[3][2];
#pragma unroll
    for (int k = 0; k < 7; ++k) { Ay[k][0] = 0.f; Ay[k][1] = 0.f; }
#pragma unroll
    for (int k = 0; k < 3; ++k) { Au[k][0] = 0.f; Au[k][1] = 0.f;
                                  Av[k][0] = 0.f; Av[k][1] = 0.f; }

    // ---- load + RGB2YUV + vertical DCT (A = D @ Xyuv), this thread's 2 cols ----
#pragma unroll
    for (int n = 0; n < 8; ++n) {
        float2 R  = *(const float2*)(pr + n * W);
        float2 G  = *(const float2*)(pg + n * W);
        float2 Bc = *(const float2*)(pb + n * W);
        float rr[2] = {R.x, R.y};
        float gg[2] = {G.x, G.y};
        float bb[2] = {Bc.x, Bc.y};
#pragma unroll
        for (int jj = 0; jj < 2; ++jj) {
            float y =  0.299f   * rr[jj] + 0.587f   * gg[jj] + 0.114f   * bb[jj];
            float u = -0.14713f * rr[jj] - 0.28886f * gg[jj] + 0.436f   * bb[jj];
            float v =  0.615f   * rr[jj] - 0.51499f * gg[jj] - 0.10001f * bb[jj];
#pragma unroll
            for (int k = 0; k < 7; ++k) Ay[k][jj] = fmaf(D[k][n], y, Ay[k][jj]);
#pragma unroll
            for (int k = 0; k < 3; ++k) Au[k][jj] = fmaf(D[k][n], u, Au[k][jj]);
#pragma unroll
            for (int k = 0; k < 3; ++k) Av[k][jj] = fmaf(D[k][n], v, Av[k][jj]);
        }
    }

    // ---- horizontal DCT (kept prefix) + horizontal inverse, in place ----
    // B[k][l] = sum_{j=0..7} A[k][j] D[l][j] : partial over own 2 cols,
    // all-reduced across the tile's 4 lanes via shfl_xor(1), shfl_xor(2).
    // Store back: A[k][jj] := 0.5*B[0] + sum_{1<=l<c} Wl[l][jj]*B[l]
    // (the overall 1/16 IDCT scaling is deferred: 1/4 here folded as 0.5/B0-free form,
    //  remaining 1/4 folded into stage-3 immediates)

#pragma unroll
    for (int k = 0; k < 7; ++k) {  // Y
        float Bv[6];
        const int c = CNTY[k];
#pragma unroll
        for (int l = 0; l < 6; ++l) {
            if (l < c) {
                float p;
                if (l == 0) p = Ay[k][0] + Ay[k][1];
                else {
                    p = Ay[k][0] * Wl[l][0];
                    p = fmaf(Ay[k][1], Wl[l][1], p);
                }
                p += __shfl_xor_sync(0xffffffffu, p, 1);
                p += __shfl_xor_sync(0xffffffffu, p, 2);
                Bv[l] = p;
            }
        }
        const float b0 = 0.5f * Bv[0];
#pragma unroll
        for (int jj = 0; jj < 2; ++jj) {
            float s = b0;
#pragma unroll
            for (int l = 1; l < 6; ++l)
                if (l < c) s = fmaf(Bv[l], Wl[l][jj], s);
            Ay[k][jj] = s;
        }
    }
#pragma unroll
    for (int k = 0; k < 3; ++k) {  // U
        float Bv[4];
        const int c = CNTC[k];
#pragma unroll
        for (int l = 0; l < 4; ++l) {
            if (l < c) {
                float p;
                if (l == 0) p = Au[k][0] + Au[k][1];
                else {
                    p = Au[k][0] * Wl[l][0];
                    p = fmaf(Au[k][1], Wl[l][1], p);
                }
                p += __shfl_xor_sync(0xffffffffu, p, 1);
                p += __shfl_xor_sync(0xffffffffu, p, 2);
                Bv[l] = p;
            }
        }
        const float b0 = 0.5f * Bv[0];
#pragma unroll
        for (int jj = 0; jj < 2; ++jj) {
            float s = b0;
#pragma unroll
            for (int l = 1; l < 4; ++l)
                if (l < c) s = fmaf(Bv[l], Wl[l][jj], s);
            Au[k][jj] = s;
        }
    }
#pragma unroll
    for (int k = 0; k < 3; ++k) {  // V
        float Bv[4];
        const int c = CNTC[k];
#pragma unroll
        for (int l = 0; l < 4; ++l) {
            if (l < c) {
                float p;
                if (l == 0) p = Av[k][0] + Av[k][1];
                else {
                    p = Av[k][0] * Wl[l][0];
                    p = fmaf(Av[k][1], Wl[l][1], p);
                }
                p += __shfl_xor_sync(0xffffffffu, p, 1);
                p += __shfl_xor_sync(0xffffffffu, p, 2);
                Bv[l] = p;
            }
        }
        const float b0 = 0.5f * Bv[0];
#pragma unroll
        for (int jj = 0; jj < 2; ++jj) {
            float s = b0;
#pragma unroll
            for (int l = 1; l < 4; ++l)
                if (l < c) s = fmaf(Bv[l], Wl[l][jj], s);
            Av[k][jj] = s;
        }
    }

    // ---- vertical inverse (remaining 1/4 folded: k==0 -> 0.03125, else 0.0625*D[k][n])
    //      + YUV2RGB + coalesced float2 stores ----
    float* qr = out + base;
    float* qg = qr + S;
    float* qb = qg + S;
#pragma unroll
    for (int n = 0; n < 8; ++n) {
        float ro[2], go[2], bo[2];
#pragma unroll
        for (int jj = 0; jj < 2; ++jj) {
            float y = 0.03125f * Ay[0][jj];
#pragma unroll
            for (int k = 1; k < 7; ++k) y = fmaf(0.0625f * D[k][n], Ay[k][jj], y);
            float u = 0.03125f * Au[0][jj];
#pragma unroll
            for (int k = 1; k < 3; ++k) u = fmaf(0.0625f * D[k][n], Au[k][jj], u);
            float v = 0.03125f * Av[0][jj];
#pragma unroll
            for (int k = 1; k < 3; ++k) v = fmaf(0.0625f * D[k][n], Av[k][jj], v);
            ro[jj] = fmaf(1.13983f, v, y);
            go[jj] = fmaf(-0.5806f, v, fmaf(-0.39465f, u, y));
            bo[jj] = fmaf(2.03211f, u, y);
        }
        *(float2*)(qr + n * W) = make_float2(ro[0], ro[1]);
        *(float2*)(qg + n * W) = make_float2(go[0], go[1]);
        *(float2*)(qb + n * W) = make_float2(bo[0], bo[1]);
    }
}

extern "C" void kernel_launch(void* const* d_in, const int* in_sizes, int n_in,
                              void* d_out, int out_size)
{
    const float* in = (const float*)d_in[0];
    float* out = (float*)d_out;
    const int total = in_sizes[0];               // B*3*512*512
    const int B = total / (3 * 512 * 512);
    const int nthr = B * 64 * 64 * 4;            // 4 threads per tile
    const int threads = 128;
    const int blocks = (nthr + threads - 1) / threads;
    jpeg_fused_kernel<<<blocks, threads>>>(in, out, nthr);
}

// round 4
// speedup vs baseline: 1.1347x; 1.1347x over previous
#include <cuda_runtime.h>

// cos(pi*t/16) constants
#define CC1 0.98078528040323044913f
#define CC2 0.92387953251128675613f
#define CC3 0.83146961230254523708f
#define CC4 0.70710678118654752440f
#define CC5 0.55557023301960222474f
#define CC6 0.38268343236508977173f
#define CC7 0.19509032201612826785f

// Four threads per 8x8 tile: thread q = g&3 owns columns {2q, 2q+1}.
// Vertical stages use the DCT even/odd row symmetry (rows n and 7-n) to halve
// accumulation FMAs. Horizontal stage couples the 4 lanes of a tile via
// shfl_xor(1)+shfl_xor(2) all-reduce per kept zigzag coefficient.
__global__ void __launch_bounds__(128, 7)
jpeg_fused_kernel(const float* __restrict__ in, float* __restrict__ out, int nthr)
{
    const int g = blockIdx.x * blockDim.x + threadIdx.x;
    if (g >= nthr) return;
    const int tile = g >> 2;
    const int q = g & 3;            // column pair index

    // D[k][n] = cos(pi/8 * (n+0.5) * k)
    const float D[8][8] = {
        { 1.f,  1.f,  1.f,  1.f,  1.f,  1.f,  1.f,  1.f},
        { CC1,  CC3,  CC5,  CC7, -CC7, -CC5, -CC3, -CC1},
        { CC2,  CC6, -CC6, -CC2, -CC2, -CC6,  CC6,  CC2},
        { CC3, -CC7, -CC1, -CC5,  CC5,  CC1,  CC7, -CC3},
        { CC4, -CC4, -CC4,  CC4,  CC4, -CC4, -CC4,  CC4},
        { CC5, -CC1,  CC7,  CC3, -CC3, -CC7,  CC1, -CC5},
        { CC6, -CC2,  CC2, -CC6, -CC6,  CC2, -CC2,  CC6},
        { CC7, -CC5,  CC3, -CC1,  CC1, -CC3,  CC5, -CC7}
    };
    // zigzag keep masks are per-row prefixes:
    const int CNTY[7] = {6,5,4,4,3,2,1}; // Y: 25 coeffs, rows 0..6
    const int CNTC[3] = {4,3,2};         // U,V: 9 coeffs, rows 0..2

    // Lane-dependent horizontal constants Wl[l][jj] = D[l][2q+jj], l=1..5.
    float Wl[6][2];
#pragma unroll
    for (int l = 1; l < 6; ++l) {
        Wl[l][0] = (q & 2) ? ((q & 1) ? D[l][6] : D[l][4])
                           : ((q & 1) ? D[l][2] : D[l][0]);
        Wl[l][1] = (q & 2) ? ((q & 1) ? D[l][7] : D[l][5])
                           : ((q & 1) ? D[l][3] : D[l][1]);
    }

    const int W = 512;
    const int S = 512 * 512;

    const int b  = tile >> 12;       // tiles per image = 64*64
    const int t  = tile & 4095;
    const int ty = t >> 6;
    const int tx = t & 63;

    const size_t base = (size_t)b * (3 * S) + (size_t)(ty * 8) * W
                      + (size_t)(tx * 8) + (size_t)(q * 2);
    const float* pr = in + base;
    const float* pg = pr + S;
    const float* pb = pg + S;

    float Ay[7][2];
    float Au[3][2];
    float Av[3][2];
#pragma unroll
    for (int k = 0; k < 7; ++k) { Ay[k][0] = 0.f; Ay[k][1] = 0.f; }
#pragma unroll
    for (int k = 0; k < 3; ++k) { Au[k][0] = 0.f; Au[k][1] = 0.f;
                                  Av[k][0] = 0.f; Av[k][1] = 0.f; }

    // ---- stage 1: load rows (p, 7-p) + RGB2YUV + even/odd vertical DCT ----
#pragma unroll
    for (int p = 0; p < 4; ++p) {
        const int n2 = 7 - p;
        float2 R0 = *(const float2*)(pr + p  * W);
        float2 G0 = *(const float2*)(pg + p  * W);
        float2 B0 = *(const float2*)(pb + p  * W);
        float2 R1 = *(const float2*)(pr + n2 * W);
        float2 G1 = *(const float2*)(pg + n2 * W);
        float2 B1 = *(const float2*)(pb + n2 * W);
        float r0[2] = {R0.x, R0.y}, g0[2] = {G0.x, G0.y}, b0[2] = {B0.x, B0.y};
        float r1[2] = {R1.x, R1.y}, g1[2] = {G1.x, G1.y}, b1[2] = {B1.x, B1.y};
#pragma unroll
        for (int jj = 0; jj < 2; ++jj) {
            float ya =  0.299f   * r0[jj] + 0.587f   * g0[jj] + 0.114f   * b0[jj];
            float ua = -0.14713f * r0[jj] - 0.28886f * g0[jj] + 0.436f   * b0[jj];
            float va =  0.615f   * r0[jj] - 0.51499f * g0[jj] - 0.10001f * b0[jj];
            float yb =  0.299f   * r1[jj] + 0.587f   * g1[jj] + 0.114f   * b1[jj];
            float ub = -0.14713f * r1[jj] - 0.28886f * g1[jj] + 0.436f   * b1[jj];
            float vb =  0.615f   * r1[jj] - 0.51499f * g1[jj] - 0.10001f * b1[jj];
            float sy = ya + yb, dy = ya - yb;
            float su = ua + ub, du = ua - ub;
            float sv = va + vb, dv = va - vb;
            // even k use s, odd k use d (D[k][7-p] = (-1)^k D[k][p])
            Ay[0][jj] += sy;
            Ay[2][jj] = fmaf(D[2][p], sy, Ay[2][jj]);
            Ay[4][jj] = fmaf(D[4][p], sy, Ay[4][jj]);
            Ay[6][jj] = fmaf(D[6][p], sy, Ay[6][jj]);
            Ay[1][jj] = fmaf(D[1][p], dy, Ay[1][jj]);
            Ay[3][jj] = fmaf(D[3][p], dy, Ay[3][jj]);
            Ay[5][jj] = fmaf(D[5][p], dy, Ay[5][jj]);
            Au[0][jj] += su;
            Au[2][jj] = fmaf(D[2][p], su, Au[2][jj]);
            Au[1][jj] = fmaf(D[1][p], du, Au[1][jj]);
            Av[0][jj] += sv;
            Av[2][jj] = fmaf(D[2][p], sv, Av[2][jj]);
            Av[1][jj] = fmaf(D[1][p], dv, Av[1][jj]);
        }
    }

    // ---- stage 2: horizontal DCT (kept prefix) + horizontal inverse, in place ----
    // B[k][l] = sum_{j=0..7} A[k][j] D[l][j]: partial over own 2 cols,
    // all-reduced across the tile's 4 lanes via shfl_xor(1), shfl_xor(2).
    // Store back: A[k][jj] := 0.5*B[0] + sum_{1<=l<c} Wl[l][jj]*B[l]
    // (overall 1/16 IDCT scaling: 1/4 folded here, 1/4 into stage-3 immediates)
#pragma unroll
    for (int k = 0; k < 7; ++k) {  // Y
        float Bv[6];
        const int c = CNTY[k];
#pragma unroll
        for (int l = 0; l < 6; ++l) {
            if (l < c) {
                float p;
                if (l == 0) p = Ay[k][0] + Ay[k][1];
                else {
                    p = Ay[k][0] * Wl[l][0];
                    p = fmaf(Ay[k][1], Wl[l][1], p);
                }
                p += __shfl_xor_sync(0xffffffffu, p, 1);
                p += __shfl_xor_sync(0xffffffffu, p, 2);
                Bv[l] = p;
            }
        }
        const float b0 = 0.5f * Bv[0];
#pragma unroll
        for (int jj = 0; jj < 2; ++jj) {
            float s = b0;
#pragma unroll
            for (int l = 1; l < 6; ++l)
                if (l < c) s = fmaf(Bv[l], Wl[l][jj], s);
            Ay[k][jj] = s;
        }
    }
#pragma unroll
    for (int k = 0; k < 3; ++k) {  // U
        float Bv[4];
        const int c = CNTC[k];
#pragma unroll
        for (int l = 0; l < 4; ++l) {
            if (l < c) {
                float p;
                if (l == 0) p = Au[k][0] + Au[k][1];
                else {
                    p = Au[k][0] * Wl[l][0];
                    p = fmaf(Au[k][1], Wl[l][1], p);
                }
                p += __shfl_xor_sync(0xffffffffu, p, 1);
                p += __shfl_xor_sync(0xffffffffu, p, 2);
                Bv[l] = p;
            }
        }
        const float b0 = 0.5f * Bv[0];
#pragma unroll
        for (int jj = 0; jj < 2; ++jj) {
            float s = b0;
#pragma unroll
            for (int l = 1; l < 4; ++l)
                if (l < c) s = fmaf(Bv[l], Wl[l][jj], s);
            Au[k][jj] = s;
        }
    }
#pragma unroll
    for (int k = 0; k < 3; ++k) {  // V
        float Bv[4];
        const int c = CNTC[k];
#pragma unroll
        for (int l = 0; l < 4; ++l) {
            if (l < c) {
                float p;
                if (l == 0) p = Av[k][0] + Av[k][1];
                else {
                    p = Av[k][0] * Wl[l][0];
                    p = fmaf(Av[k][1], Wl[l][1], p);
                }
                p += __shfl_xor_sync(0xffffffffu, p, 1);
                p += __shfl_xor_sync(0xffffffffu, p, 2);
                Bv[l] = p;
            }
        }
        const float b0 = 0.5f * Bv[0];
#pragma unroll
        for (int jj = 0; jj < 2; ++jj) {
            float s = b0;
#pragma unroll
            for (int l = 1; l < 4; ++l)
                if (l < c) s = fmaf(Bv[l], Wl[l][jj], s);
            Av[k][jj] = s;
        }
    }

    // ---- stage 3: even/odd vertical inverse + YUV2RGB + coalesced stores ----
    // ID'[n][k] = (k==0) ? 0.03125 : 0.0625*D[k][n]; rows p and 7-p are e +/- o.
    float* qr = out + base;
    float* qg = qr + S;
    float* qb = qg + S;
#pragma unroll
    for (int p = 0; p < 4; ++p) {
        const int n2 = 7 - p;
        float roA[2], goA[2], boA[2], roB[2], goB[2], boB[2];
#pragma unroll
        for (int jj = 0; jj < 2; ++jj) {
            float ey = 0.03125f * Ay[0][jj];
            ey = fmaf(0.0625f * D[2][p], Ay[2][jj], ey);
            ey = fmaf(0.0625f * D[4][p], Ay[4][jj], ey);
            ey = fmaf(0.0625f * D[6][p], Ay[6][jj], ey);
            float oy = 0.0625f * D[1][p] * Ay[1][jj];
            oy = fmaf(0.0625f * D[3][p], Ay[3][jj], oy);
            oy = fmaf(0.0625f * D[5][p], Ay[5][jj], oy);
            float eu = 0.03125f * Au[0][jj];
            eu = fmaf(0.0625f * D[2][p], Au[2][jj], eu);
            float ou = 0.0625f * D[1][p] * Au[1][jj];
            float ev = 0.03125f * Av[0][jj];
            ev = fmaf(0.0625f * D[2][p], Av[2][jj], ev);
            float ov = 0.0625f * D[1][p] * Av[1][jj];

            float yA = ey + oy, yB = ey - oy;
            float uA = eu + ou, uB = eu - ou;
            float vA = ev + ov, vB = ev - ov;

            roA[jj] = fmaf(1.13983f, vA, yA);
            goA[jj] = fmaf(-0.5806f, vA, fmaf(-0.39465f, uA, yA));
            boA[jj] = fmaf(2.03211f, uA, yA);
            roB[jj] = fmaf(1.13983f, vB, yB);
            goB[jj] = fmaf(-0.5806f, vB, fmaf(-0.39465f, uB, yB));
            boB[jj] = fmaf(2.03211f, uB, yB);
        }
        *(float2*)(qr + p  * W) = make_float2(roA[0], roA[1]);
        *(float2*)(qg + p  * W) = make_float2(goA[0], goA[1]);
        *(float2*)(qb + p  * W) = make_float2(boA[0], boA[1]);
        *(float2*)(qr + n2 * W) = make_float2(roB[0], roB[1]);
        *(float2*)(qg + n2 * W) = make_float2(goB[0], goB[1]);
        *(float2*)(qb + n2 * W) = make_float2(boB[0], boB[1]);
    }
}

extern "C" void kernel_launch(void* const* d_in, const int* in_sizes, int n_in,
                              void* d_out, int out_size)
{
    const float* in = (const float*)d_in[0];
    float* out = (float*)d_out;
    const int total = in_sizes[0];               // B*3*512*512
    const int B = total / (3 * 512 * 512);
    const int nthr = B * 64 * 64 * 4;            // 4 threads per tile
    const int threads = 128;
    const int blocks = (nthr + threads - 1) / threads;
    jpeg_fused_kernel<<<blocks, threads>>>(in, out, nthr);
}